// round 9
// baseline (speedup 1.0000x reference)
#include <cuda_runtime.h>
#include <cuda_fp16.h>
#include <cstdint>
#include <math.h>

// ---------------------------------------------------------------------------
// SoftEmbRescore (sm_100 base ISA — tcgen05 unavailable in this build):
//   G    = emb @ emb^T      (tf32 mma.sync, 1024x1024, stored as fp16)
//   x_h  = fp16(x)          (pre-pass, 128 MB scratch)
//   dots = x_h @ G_h        (fp16 m16n8k16 mma.sync)
//   out[i,j] = dots[i,j] / max(s_i * e_j, 1e-8)
//     e_j = sqrt(G[j,j]);  s_i = sqrt(sum_j dots[i,j]*x[i,j])   (row-local)
// R9 == R8 resubmit (R8 bench died to container-level failure with no kernel
// signal; kernel audited clean: 2 CTAs/SM, 221 KB/SM smem, ~113 live regs
// under the 128-reg cap). 128x128 CTA tile, 64x32 warp tile, 3-stage cp.async.
// ---------------------------------------------------------------------------

namespace {
constexpr int MDIM = 65536;
constexpr int NDIM = 1024;
constexpr int KDIM = 1024;

// ---- main GEMM tiling (fp16) ----
constexpr int BM = 128;
constexpr int BN = 128;
constexpr int BK = 64;                           // 128 B rows
constexpr int LDSH = BK + 8;                     // 72 halves = 144 B rows
constexpr int NTHREADS = 256;
constexpr int NSTAGE = 3;
constexpr int NT = KDIM / BK;                    // 16
constexpr int STAGE_HALVES = (BM + BN) * LDSH;   // 18432 halves = 36864 B
constexpr int SMEM_MAIN = NSTAGE * STAGE_HALVES * 2;  // 110592 B -> 2 CTAs/SM

// ---- G-builder tiling (tf32 mma.sync, 64 CTAs) ----
constexpr int GBM = 128, GBN = 128, GBK = 16;
constexpr int GLDS = GBK + 4;
constexpr int GNT = KDIM / GBK;
constexpr int GSTAGE = (GBM + GBN) * GLDS;
}

__device__ __align__(16) __half g_h[(size_t)NDIM * NDIM];     // 2 MB
__device__ __align__(16) __half x_h[(size_t)MDIM * KDIM];     // 128 MB
__device__ __align__(16) float e_norm[NDIM];

// ============================ helpers ======================================

__device__ __forceinline__ uint32_t smem_u32(const void* p) {
    uint32_t a;
    asm("{ .reg .u64 t; cvta.to.shared.u64 t, %1; cvt.u32.u64 %0, t; }" : "=r"(a) : "l"(p));
    return a;
}
__device__ __forceinline__ uint32_t f2tf32(float f) {
    uint32_t r;
    asm("cvt.rna.tf32.f32 %0, %1;" : "=r"(r) : "f"(f));
    return r;
}
__device__ __forceinline__ void mma_tf32(float* d, const uint32_t* a, const uint32_t* b) {
    asm volatile(
        "mma.sync.aligned.m16n8k8.row.col.f32.tf32.tf32.f32 "
        "{%0,%1,%2,%3}, {%4,%5,%6,%7}, {%8,%9}, {%0,%1,%2,%3};"
        : "+f"(d[0]), "+f"(d[1]), "+f"(d[2]), "+f"(d[3])
        : "r"(a[0]), "r"(a[1]), "r"(a[2]), "r"(a[3]), "r"(b[0]), "r"(b[1]));
}
__device__ __forceinline__ void mma_f16(float* d, const uint32_t* a, const uint32_t* b) {
    asm volatile(
        "mma.sync.aligned.m16n8k16.row.col.f32.f16.f16.f32 "
        "{%0,%1,%2,%3}, {%4,%5,%6,%7}, {%8,%9}, {%0,%1,%2,%3};"
        : "+f"(d[0]), "+f"(d[1]), "+f"(d[2]), "+f"(d[3])
        : "r"(a[0]), "r"(a[1]), "r"(a[2]), "r"(a[3]), "r"(b[0]), "r"(b[1]));
}

#define CP_ASYNC16(dst, src) \
    asm volatile("cp.async.cg.shared.global [%0], [%1], 16;" :: "r"(dst), "l"(src))
#define CP_COMMIT() asm volatile("cp.async.commit_group;")
#define CP_WAIT2()  asm volatile("cp.async.wait_group 2;")
#define CP_WAIT1()  asm volatile("cp.async.wait_group 1;")
#define CP_WAIT0()  asm volatile("cp.async.wait_group 0;")

// ================= kernel 0: x -> fp16 (8 elems/thread) ====================

__global__ __launch_bounds__(256) void cvt_x_kernel(const float* __restrict__ x) {
    size_t i = ((size_t)blockIdx.x * 256 + threadIdx.x) * 8;
    float4 v0 = *reinterpret_cast<const float4*>(x + i);
    float4 v1 = *reinterpret_cast<const float4*>(x + i + 4);
    __half2 h[4];
    h[0] = __floats2half2_rn(v0.x, v0.y);
    h[1] = __floats2half2_rn(v0.z, v0.w);
    h[2] = __floats2half2_rn(v1.x, v1.y);
    h[3] = __floats2half2_rn(v1.z, v1.w);
    *reinterpret_cast<uint4*>(x_h + i) = *reinterpret_cast<uint4*>(h);
}

// ========= kernel 1: G = emb @ emb^T (tf32 compute, fp16 store) ============

__global__ __launch_bounds__(256, 2)
void g_gemm_kernel(const float* __restrict__ A)
{
    __shared__ __align__(16) float smem[2 * GSTAGE];
    const int tid = threadIdx.x;
    const int m0 = blockIdx.y * GBM;
    const int n0 = blockIdx.x * GBN;

    auto load_stage = [&](int s, int kt) {
        const float* Ag = A + (size_t)m0 * KDIM + kt * GBK;
        const float* Bg = A + (size_t)n0 * KDIM + kt * GBK;
        float* Asm = smem + s * GSTAGE;
        float* Bsm = Asm + GBM * GLDS;
        #pragma unroll
        for (int i = 0; i < 2; ++i) {
            int chunk = tid + i * 256;
            int r = chunk >> 2;
            int c = (chunk & 3) * 4;
            CP_ASYNC16(smem_u32(Asm + r * GLDS + c), Ag + (size_t)r * KDIM + c);
            CP_ASYNC16(smem_u32(Bsm + r * GLDS + c), Bg + (size_t)r * KDIM + c);
        }
        CP_COMMIT();
    };

    const int warp = tid >> 5, lane = tid & 31;
    const int mb = (warp & 3) * 32, nb = (warp >> 2) * 64;
    const int grp = lane >> 2, tig = lane & 3;

    float d[2][8][4];
    #pragma unroll
    for (int mi = 0; mi < 2; ++mi)
        #pragma unroll
        for (int ni = 0; ni < 8; ++ni)
            #pragma unroll
            for (int r = 0; r < 4; ++r) d[mi][ni][r] = 0.f;

    load_stage(0, 0);
    for (int t = 0; t < GNT; ++t) {
        if (t + 1 < GNT) { load_stage((t + 1) & 1, t + 1); CP_WAIT1(); }
        else             { CP_WAIT0(); }
        __syncthreads();
        const float* Asm = smem + (t & 1) * GSTAGE;
        const float* Bsm = Asm + GBM * GLDS;
        #pragma unroll
        for (int kk = 0; kk < GBK; kk += 8) {
            uint32_t a[2][4];
            #pragma unroll
            for (int mi = 0; mi < 2; ++mi) {
                const float* p = Asm + (mb + mi * 16 + grp) * GLDS + kk + tig;
                a[mi][0] = f2tf32(p[0]);
                a[mi][1] = f2tf32(p[8 * GLDS]);
                a[mi][2] = f2tf32(p[4]);
                a[mi][3] = f2tf32(p[8 * GLDS + 4]);
            }
            uint32_t b[8][2];
            #pragma unroll
            for (int ni = 0; ni < 8; ++ni) {
                const float* p = Bsm + (nb + ni * 8 + grp) * GLDS + kk + tig;
                b[ni][0] = f2tf32(p[0]);
                b[ni][1] = f2tf32(p[4]);
            }
            #pragma unroll
            for (int mi = 0; mi < 2; ++mi)
                #pragma unroll
                for (int ni = 0; ni < 8; ++ni)
                    mma_tf32(d[mi][ni], a[mi], b[ni]);
        }
        __syncthreads();
    }
    // store G as fp16 (the exact operand the main GEMM consumes)
    #pragma unroll
    for (int mi = 0; mi < 2; ++mi) {
        #pragma unroll
        for (int ni = 0; ni < 8; ++ni) {
            int row = m0 + mb + mi * 16 + grp;
            int col = n0 + nb + ni * 8 + 2 * tig;
            *reinterpret_cast<__half2*>(g_h + (size_t)row * NDIM + col) =
                __floats2half2_rn(d[mi][ni][0], d[mi][ni][1]);
            *reinterpret_cast<__half2*>(g_h + (size_t)(row + 8) * NDIM + col) =
                __floats2half2_rn(d[mi][ni][2], d[mi][ni][3]);
        }
    }
}

__global__ void diag_norm_kernel() {
    int j = blockIdx.x * blockDim.x + threadIdx.x;
    if (j < NDIM)
        e_norm[j] = sqrtf(fmaxf(__half2float(g_h[(size_t)j * NDIM + j]), 0.f));
}

// == kernel 2: dots = x_h @ G_h, fp16, 128x128 CTA, 64x32/warp, 2 CTAs/SM ===

__global__ __launch_bounds__(NTHREADS, 2)
void main_gemm_kernel(float* __restrict__ out)
{
    extern __shared__ __align__(16) __half smem_h[];
    const int tid = threadIdx.x;
    const int m0 = blockIdx.y * BM;
    const int n0 = blockIdx.x * BN;

    auto fill = [&](int kt) {
        __half* S = smem_h + (kt % NSTAGE) * STAGE_HALVES;
        const __half* Ag = x_h + (size_t)m0 * KDIM + kt * BK;
        const __half* Bg = g_h + (size_t)n0 * KDIM + kt * BK;
        #pragma unroll
        for (int i = 0; i < 8; ++i) {
            int chunk = tid + i * NTHREADS;       // 0..2047 (16B chunks)
            int r = chunk >> 3;                   // 0..255 (A 0-127, B 128-255)
            int c = (chunk & 7) * 8;              // halves: 0,8,...,56
            const __half* src = (r < BM) ? (Ag + (size_t)r * KDIM + c)
                                         : (Bg + (size_t)(r - BM) * KDIM + c);
            CP_ASYNC16(smem_u32(S + r * LDSH + c), src);
        }
        CP_COMMIT();
    };

    const int warp = tid >> 5, lane = tid & 31;
    const int mb = (warp & 1) * 64;               // 2 warps along M
    const int nb = (warp >> 1) * 32;              // 4 warps along N
    const int grp = lane >> 2, tig = lane & 3;

    float d[4][4][4];                              // 64 accum regs
    #pragma unroll
    for (int mi = 0; mi < 4; ++mi)
        #pragma unroll
        for (int ni = 0; ni < 4; ++ni)
            #pragma unroll
            for (int r = 0; r < 4; ++r) d[mi][ni][r] = 0.f;

    fill(0); fill(1);

    for (int t = 0; t < NT; ++t) {
        if (t + 2 < NT) fill(t + 2);
        else            CP_COMMIT();              // fixed group accounting
        CP_WAIT2();
        __syncthreads();

        const __half* Asm = smem_h + (t % NSTAGE) * STAGE_HALVES;
        const __half* Bsm = Asm + BM * LDSH;

        #pragma unroll
        for (int kk = 0; kk < BK; kk += 16) {
            uint32_t a[4][4];
            #pragma unroll
            for (int mi = 0; mi < 4; ++mi) {
                const __half* p = Asm + (mb + mi * 16 + grp) * LDSH + kk + 2 * tig;
                a[mi][0] = *reinterpret_cast<const uint32_t*>(p);
                a[mi][1] = *reinterpret_cast<const uint32_t*>(p + 8 * LDSH);
                a[mi][2] = *reinterpret_cast<const uint32_t*>(p + 8);
                a[mi][3] = *reinterpret_cast<const uint32_t*>(p + 8 * LDSH + 8);
            }
            uint32_t b[4][2];
            #pragma unroll
            for (int ni = 0; ni < 4; ++ni) {
                const __half* q = Bsm + (nb + ni * 8 + grp) * LDSH + kk + 2 * tig;
                b[ni][0] = *reinterpret_cast<const uint32_t*>(q);
                b[ni][1] = *reinterpret_cast<const uint32_t*>(q + 8);
            }
            #pragma unroll
            for (int mi = 0; mi < 4; ++mi)
                #pragma unroll
                for (int ni = 0; ni < 4; ++ni)
                    mma_f16(d[mi][ni], a[mi], b[ni]);
        }
        __syncthreads();
    }

    // epilogue: raw dots (finalize divides in a separate pass)
    #pragma unroll
    for (int mi = 0; mi < 4; ++mi) {
        #pragma unroll
        for (int ni = 0; ni < 4; ++ni) {
            int row = m0 + mb + mi * 16 + grp;
            int col = n0 + nb + ni * 8 + 2 * tig;
            *reinterpret_cast<float2*>(out + (size_t)row * NDIM + col) =
                make_float2(d[mi][ni][0], d[mi][ni][1]);
            *reinterpret_cast<float2*>(out + (size_t)(row + 8) * NDIM + col) =
                make_float2(d[mi][ni][2], d[mi][ni][3]);
        }
    }
}

// ===== kernel 3: finalize. s_i row-local: s^2 = sum_j dots_ij * x_ij =======

__global__ __launch_bounds__(256)
void finalize_kernel(float* __restrict__ out)
{
    __shared__ float red[8];
    const int m = blockIdx.x, t = threadIdx.x, lane = t & 31;
    float4* dp = reinterpret_cast<float4*>(out + (size_t)m * NDIM);
    float4 dv = dp[t];
    uint2 xr = *reinterpret_cast<const uint2*>(x_h + (size_t)m * NDIM + t * 4);
    float2 x01 = __half22float2(*reinterpret_cast<__half2*>(&xr.x));
    float2 x23 = __half22float2(*reinterpret_cast<__half2*>(&xr.y));
    float a = dv.x * x01.x + dv.y * x01.y + dv.z * x23.x + dv.w * x23.y;
    #pragma unroll
    for (int o = 16; o > 0; o >>= 1) a += __shfl_xor_sync(0xffffffffu, a, o);
    if (lane == 0) red[t >> 5] = a;
    __syncthreads();
    float s2 = red[0] + red[1] + red[2] + red[3] + red[4] + red[5] + red[6] + red[7];
    float s = sqrtf(fmaxf(s2, 0.f));
    float4 ev = reinterpret_cast<const float4*>(e_norm)[t];
    dv.x = __fdividef(dv.x, fmaxf(s * ev.x, 1e-8f));
    dv.y = __fdividef(dv.y, fmaxf(s * ev.y, 1e-8f));
    dv.z = __fdividef(dv.z, fmaxf(s * ev.z, 1e-8f));
    dv.w = __fdividef(dv.w, fmaxf(s * ev.w, 1e-8f));
    dp[t] = dv;
}

// ============================== launch =====================================

extern "C" void kernel_launch(void* const* d_in, const int* in_sizes, int n_in,
                              void* d_out, int out_size) {
    const float* x   = (const float*)d_in[0];   // [1, 65536, 1024] fp32
    const float* emb = (const float*)d_in[1];   // [1024, 1024] fp32
    float* out = (float*)d_out;                 // [1, 65536, 1024] fp32
    (void)in_sizes; (void)n_in; (void)out_size;

    cudaFuncSetAttribute(main_gemm_kernel,
                         cudaFuncAttributeMaxDynamicSharedMemorySize, SMEM_MAIN);

    // 0) x_h = fp16(x)
    cvt_x_kernel<<<(int)((size_t)MDIM * KDIM / 2048), 256>>>(x);
    // 1) G = emb @ emb^T (tf32 compute, fp16 store)
    g_gemm_kernel<<<dim3(NDIM / GBN, NDIM / GBM), 256>>>(emb);
    // 2) e_j = sqrt(G[j,j])
    diag_norm_kernel<<<NDIM / 256, 256>>>();
    // 3) dots = x_h @ G_h  (fp16 tensor cores, 2 CTAs/SM)
    main_gemm_kernel<<<dim3(NDIM / BN, MDIM / BM), NTHREADS, SMEM_MAIN>>>(out);
    // 4) out = dots / max(s_i * e_j, eps)
    finalize_kernel<<<MDIM, 256>>>(out);
}

// round 10
// speedup vs baseline: 1.0034x; 1.0034x over previous
#include <cuda_runtime.h>
#include <cuda_fp16.h>
#include <cstdint>
#include <math.h>

// ---------------------------------------------------------------------------
// SoftEmbRescore (sm_100 base ISA — tcgen05 unavailable in this build):
//   G    = emb @ emb^T      (tf32 mma.sync, 1024x1024, stored as fp16)
//   x_h  = fp16(x)          (pre-pass, 128 MB scratch)
//   dots = x_h @ G_h        (fp16 m16n8k16 mma.sync)
//   out[i,j] = dots[i,j] / max(s_i * e_j, 1e-8)
//     e_j = sqrt(G[j,j]);  s_i = sqrt(sum_j dots[i,j]*x[i,j])   (row-local)
// R10: smem-crossbar relief. CTA 256x128 / 512 thr / 1 CTA/SM (write traffic
// 72->48 B per HMMA, crossbar duty 97%->88%), ldmatrix.x4 operand loads
// (4x fewer LDS issues), 4-stage cp.async pipeline. 16 warps/SM retained.
// ---------------------------------------------------------------------------

namespace {
constexpr int MDIM = 65536;
constexpr int NDIM = 1024;
constexpr int KDIM = 1024;

// ---- main GEMM tiling (fp16) ----
constexpr int BM = 256;
constexpr int BN = 128;
constexpr int BK = 64;                           // 128 B rows
constexpr int LDSH = BK + 8;                     // 72 halves = 144 B rows
constexpr int NTHREADS = 512;
constexpr int NSTAGE = 4;
constexpr int NT = KDIM / BK;                    // 16
constexpr int STAGE_HALVES = (BM + BN) * LDSH;   // 27648 halves = 55296 B
constexpr int SMEM_MAIN = NSTAGE * STAGE_HALVES * 2;  // 221184 B

// ---- G-builder tiling (tf32 mma.sync, 64 CTAs) ----
constexpr int GBM = 128, GBN = 128, GBK = 16;
constexpr int GLDS = GBK + 4;
constexpr int GNT = KDIM / GBK;
constexpr int GSTAGE = (GBM + GBN) * GLDS;
}

__device__ __align__(16) __half g_h[(size_t)NDIM * NDIM];     // 2 MB
__device__ __align__(16) __half x_h[(size_t)MDIM * KDIM];     // 128 MB
__device__ __align__(16) float e_norm[NDIM];

// ============================ helpers ======================================

__device__ __forceinline__ uint32_t smem_u32(const void* p) {
    uint32_t a;
    asm("{ .reg .u64 t; cvta.to.shared.u64 t, %1; cvt.u32.u64 %0, t; }" : "=r"(a) : "l"(p));
    return a;
}
__device__ __forceinline__ uint32_t f2tf32(float f) {
    uint32_t r;
    asm("cvt.rna.tf32.f32 %0, %1;" : "=r"(r) : "f"(f));
    return r;
}
__device__ __forceinline__ void mma_tf32(float* d, const uint32_t* a, const uint32_t* b) {
    asm volatile(
        "mma.sync.aligned.m16n8k8.row.col.f32.tf32.tf32.f32 "
        "{%0,%1,%2,%3}, {%4,%5,%6,%7}, {%8,%9}, {%0,%1,%2,%3};"
        : "+f"(d[0]), "+f"(d[1]), "+f"(d[2]), "+f"(d[3])
        : "r"(a[0]), "r"(a[1]), "r"(a[2]), "r"(a[3]), "r"(b[0]), "r"(b[1]));
}
__device__ __forceinline__ void mma_f16(float* d, const uint32_t* a, const uint32_t* b) {
    asm volatile(
        "mma.sync.aligned.m16n8k16.row.col.f32.f16.f16.f32 "
        "{%0,%1,%2,%3}, {%4,%5,%6,%7}, {%8,%9}, {%0,%1,%2,%3};"
        : "+f"(d[0]), "+f"(d[1]), "+f"(d[2]), "+f"(d[3])
        : "r"(a[0]), "r"(a[1]), "r"(a[2]), "r"(a[3]), "r"(b[0]), "r"(b[1]));
}
// ldmatrix x4: lanes 0-31 supply 8-row addresses for 4 8x8 b16 matrices.
#define LDSM_X4(r0, r1, r2, r3, addr) \
    asm volatile("ldmatrix.sync.aligned.m8n8.x4.shared.b16 {%0,%1,%2,%3}, [%4];" \
                 : "=r"(r0), "=r"(r1), "=r"(r2), "=r"(r3) : "r"(addr))

#define CP_ASYNC16(dst, src) \
    asm volatile("cp.async.cg.shared.global [%0], [%1], 16;" :: "r"(dst), "l"(src))
#define CP_COMMIT() asm volatile("cp.async.commit_group;")
#define CP_WAIT3()  asm volatile("cp.async.wait_group 3;")
#define CP_WAIT1()  asm volatile("cp.async.wait_group 1;")
#define CP_WAIT0()  asm volatile("cp.async.wait_group 0;")

// ================= kernel 0: x -> fp16 (8 elems/thread) ====================

__global__ __launch_bounds__(256) void cvt_x_kernel(const float* __restrict__ x) {
    size_t i = ((size_t)blockIdx.x * 256 + threadIdx.x) * 8;
    float4 v0 = *reinterpret_cast<const float4*>(x + i);
    float4 v1 = *reinterpret_cast<const float4*>(x + i + 4);
    __half2 h[4];
    h[0] = __floats2half2_rn(v0.x, v0.y);
    h[1] = __floats2half2_rn(v0.z, v0.w);
    h[2] = __floats2half2_rn(v1.x, v1.y);
    h[3] = __floats2half2_rn(v1.z, v1.w);
    *reinterpret_cast<uint4*>(x_h + i) = *reinterpret_cast<uint4*>(h);
}

// ========= kernel 1: G = emb @ emb^T (tf32 compute, fp16 store) ============

__global__ __launch_bounds__(256, 2)
void g_gemm_kernel(const float* __restrict__ A)
{
    __shared__ __align__(16) float smem[2 * GSTAGE];
    const int tid = threadIdx.x;
    const int m0 = blockIdx.y * GBM;
    const int n0 = blockIdx.x * GBN;

    auto load_stage = [&](int s, int kt) {
        const float* Ag = A + (size_t)m0 * KDIM + kt * GBK;
        const float* Bg = A + (size_t)n0 * KDIM + kt * GBK;
        float* Asm = smem + s * GSTAGE;
        float* Bsm = Asm + GBM * GLDS;
        #pragma unroll
        for (int i = 0; i < 2; ++i) {
            int chunk = tid + i * 256;
            int r = chunk >> 2;
            int c = (chunk & 3) * 4;
            CP_ASYNC16(smem_u32(Asm + r * GLDS + c), Ag + (size_t)r * KDIM + c);
            CP_ASYNC16(smem_u32(Bsm + r * GLDS + c), Bg + (size_t)r * KDIM + c);
        }
        CP_COMMIT();
    };

    const int warp = tid >> 5, lane = tid & 31;
    const int mb = (warp & 3) * 32, nb = (warp >> 2) * 64;
    const int grp = lane >> 2, tig = lane & 3;

    float d[2][8][4];
    #pragma unroll
    for (int mi = 0; mi < 2; ++mi)
        #pragma unroll
        for (int ni = 0; ni < 8; ++ni)
            #pragma unroll
            for (int r = 0; r < 4; ++r) d[mi][ni][r] = 0.f;

    load_stage(0, 0);
    for (int t = 0; t < GNT; ++t) {
        if (t + 1 < GNT) { load_stage((t + 1) & 1, t + 1); CP_WAIT1(); }
        else             { CP_WAIT0(); }
        __syncthreads();
        const float* Asm = smem + (t & 1) * GSTAGE;
        const float* Bsm = Asm + GBM * GLDS;
        #pragma unroll
        for (int kk = 0; kk < GBK; kk += 8) {
            uint32_t a[2][4];
            #pragma unroll
            for (int mi = 0; mi < 2; ++mi) {
                const float* p = Asm + (mb + mi * 16 + grp) * GLDS + kk + tig;
                a[mi][0] = f2tf32(p[0]);
                a[mi][1] = f2tf32(p[8 * GLDS]);
                a[mi][2] = f2tf32(p[4]);
                a[mi][3] = f2tf32(p[8 * GLDS + 4]);
            }
            uint32_t b[8][2];
            #pragma unroll
            for (int ni = 0; ni < 8; ++ni) {
                const float* p = Bsm + (nb + ni * 8 + grp) * GLDS + kk + tig;
                b[ni][0] = f2tf32(p[0]);
                b[ni][1] = f2tf32(p[4]);
            }
            #pragma unroll
            for (int mi = 0; mi < 2; ++mi)
                #pragma unroll
                for (int ni = 0; ni < 8; ++ni)
                    mma_tf32(d[mi][ni], a[mi], b[ni]);
        }
        __syncthreads();
    }
    // store G as fp16 (the exact operand the main GEMM consumes)
    #pragma unroll
    for (int mi = 0; mi < 2; ++mi) {
        #pragma unroll
        for (int ni = 0; ni < 8; ++ni) {
            int row = m0 + mb + mi * 16 + grp;
            int col = n0 + nb + ni * 8 + 2 * tig;
            *reinterpret_cast<__half2*>(g_h + (size_t)row * NDIM + col) =
                __floats2half2_rn(d[mi][ni][0], d[mi][ni][1]);
            *reinterpret_cast<__half2*>(g_h + (size_t)(row + 8) * NDIM + col) =
                __floats2half2_rn(d[mi][ni][2], d[mi][ni][3]);
        }
    }
}

__global__ void diag_norm_kernel() {
    int j = blockIdx.x * blockDim.x + threadIdx.x;
    if (j < NDIM)
        e_norm[j] = sqrtf(fmaxf(__half2float(g_h[(size_t)j * NDIM + j]), 0.f));
}

// == kernel 2: dots = x_h @ G_h; CTA 256x128, 512 thr, 64x32/warp, ldmatrix ==

__global__ __launch_bounds__(NTHREADS, 1)
void main_gemm_kernel(float* __restrict__ out)
{
    extern __shared__ __align__(16) __half smem_h[];
    const int tid = threadIdx.x;
    const int m0 = blockIdx.y * BM;
    const int n0 = blockIdx.x * BN;

    auto fill = [&](int kt) {
        __half* S = smem_h + (kt & 3) * STAGE_HALVES;
        const __half* Ag = x_h + (size_t)m0 * KDIM + kt * BK;
        const __half* Bg = g_h + (size_t)n0 * KDIM + kt * BK;
        #pragma unroll
        for (int i = 0; i < 6; ++i) {
            int chunk = tid + i * NTHREADS;       // 0..3071 (16B chunks)
            int r = chunk >> 3;                   // 0..383 (A 0-255, B 256-383)
            int c = (chunk & 7) * 8;              // halves: 0,8,...,56
            const __half* src = (r < BM) ? (Ag + (size_t)r * KDIM + c)
                                         : (Bg + (size_t)(r - BM) * KDIM + c);
            CP_ASYNC16(smem_u32(S + r * LDSH + c), src);
        }
        CP_COMMIT();
    };

    const int warp = tid >> 5, lane = tid & 31;
    const int mb = (warp & 3) * 64;               // 4 warps along M (256)
    const int nb = (warp >> 2) * 32;              // 4 warps along N (128)
    const int grp = lane >> 2, tig = lane & 3;

    // ldmatrix lane->row maps (in halves, relative to A-base / B-base of stage)
    // A x4 for one 16x16 frag: lanes 0-15 -> rows 0-15 @k0, 16-31 -> rows @k+8.
    const int a_lane_off = (mb + (lane & 15)) * LDSH + (lane >> 4) * 8;
    // B x4 covers 2 adjacent n8 groups: lanes 0-7 n0-7@k0, 8-15 n0-7@k8,
    // 16-23 n8-15@k0, 24-31 n8-15@k8.
    const int b_lane_off = (nb + (lane & 7) + ((lane >> 4) * 8)) * LDSH
                         + ((lane >> 3) & 1) * 8;

    float d[4][4][4];                              // 64 accum regs
    #pragma unroll
    for (int mi = 0; mi < 4; ++mi)
        #pragma unroll
        for (int ni = 0; ni < 4; ++ni)
            #pragma unroll
            for (int r = 0; r < 4; ++r) d[mi][ni][r] = 0.f;

    fill(0); fill(1); fill(2);

    for (int t = 0; t < NT; ++t) {
        if (t + 3 < NT) fill(t + 3);
        else            CP_COMMIT();              // fixed group accounting
        CP_WAIT3();                               // stage t complete
        __syncthreads();

        const __half* As = smem_h + (t & 3) * STAGE_HALVES;
        const uint32_t a_base = smem_u32(As) + (uint32_t)a_lane_off * 2;
        const uint32_t b_base = smem_u32(As + BM * LDSH) + (uint32_t)b_lane_off * 2;

        #pragma unroll
        for (int kk = 0; kk < BK; kk += 16) {
            uint32_t a[4][4];
            #pragma unroll
            for (int mi = 0; mi < 4; ++mi)
                LDSM_X4(a[mi][0], a[mi][1], a[mi][2], a[mi][3],
                        a_base + (mi * 16 * LDSH + kk) * 2);
            uint32_t b[2][4];                      // [nj][{b(2nj).0,.1,b(2nj+1).0,.1}]
            #pragma unroll
            for (int nj = 0; nj < 2; ++nj)
                LDSM_X4(b[nj][0], b[nj][1], b[nj][2], b[nj][3],
                        b_base + (nj * 16 * LDSH + kk) * 2);
            #pragma unroll
            for (int mi = 0; mi < 4; ++mi)
                #pragma unroll
                for (int ni = 0; ni < 4; ++ni)
                    mma_f16(d[mi][ni], a[mi], &b[ni >> 1][(ni & 1) * 2]);
        }
        __syncthreads();
    }

    // epilogue: raw dots (finalize divides in a separate pass)
    #pragma unroll
    for (int mi = 0; mi < 4; ++mi) {
        #pragma unroll
        for (int ni = 0; ni < 4; ++ni) {
            int row = m0 + mb + mi * 16 + grp;
            int col = n0 + nb + ni * 8 + 2 * tig;
            *reinterpret_cast<float2*>(out + (size_t)row * NDIM + col) =
                make_float2(d[mi][ni][0], d[mi][ni][1]);
            *reinterpret_cast<float2*>(out + (size_t)(row + 8) * NDIM + col) =
                make_float2(d[mi][ni][2], d[mi][ni][3]);
        }
    }
}

// ===== kernel 3: finalize. s_i row-local: s^2 = sum_j dots_ij * x_ij =======

__global__ __launch_bounds__(256)
void finalize_kernel(float* __restrict__ out)
{
    __shared__ float red[8];
    const int m = blockIdx.x, t = threadIdx.x, lane = t & 31;
    float4* dp = reinterpret_cast<float4*>(out + (size_t)m * NDIM);
    float4 dv = dp[t];
    uint2 xr = *reinterpret_cast<const uint2*>(x_h + (size_t)m * NDIM + t * 4);
    float2 x01 = __half22float2(*reinterpret_cast<__half2*>(&xr.x));
    float2 x23 = __half22float2(*reinterpret_cast<__half2*>(&xr.y));
    float a = dv.x * x01.x + dv.y * x01.y + dv.z * x23.x + dv.w * x23.y;
    #pragma unroll
    for (int o = 16; o > 0; o >>= 1) a += __shfl_xor_sync(0xffffffffu, a, o);
    if (lane == 0) red[t >> 5] = a;
    __syncthreads();
    float s2 = red[0] + red[1] + red[2] + red[3] + red[4] + red[5] + red[6] + red[7];
    float s = sqrtf(fmaxf(s2, 0.f));
    float4 ev = reinterpret_cast<const float4*>(e_norm)[t];
    dv.x = __fdividef(dv.x, fmaxf(s * ev.x, 1e-8f));
    dv.y = __fdividef(dv.y, fmaxf(s * ev.y, 1e-8f));
    dv.z = __fdividef(dv.z, fmaxf(s * ev.z, 1e-8f));
    dv.w = __fdividef(dv.w, fmaxf(s * ev.w, 1e-8f));
    dp[t] = dv;
}

// ============================== launch =====================================

extern "C" void kernel_launch(void* const* d_in, const int* in_sizes, int n_in,
                              void* d_out, int out_size) {
    const float* x   = (const float*)d_in[0];   // [1, 65536, 1024] fp32
    const float* emb = (const float*)d_in[1];   // [1024, 1024] fp32
    float* out = (float*)d_out;                 // [1, 65536, 1024] fp32
    (void)in_sizes; (void)n_in; (void)out_size;

    cudaFuncSetAttribute(main_gemm_kernel,
                         cudaFuncAttributeMaxDynamicSharedMemorySize, SMEM_MAIN);

    // 0) x_h = fp16(x)
    cvt_x_kernel<<<(int)((size_t)MDIM * KDIM / 2048), 256>>>(x);
    // 1) G = emb @ emb^T (tf32 compute, fp16 store)
    g_gemm_kernel<<<dim3(NDIM / GBN, NDIM / GBM), 256>>>(emb);
    // 2) e_j = sqrt(G[j,j])
    diag_norm_kernel<<<NDIM / 256, 256>>>();
    // 3) dots = x_h @ G_h  (fp16 tensor cores, ldmatrix operand loads)
    main_gemm_kernel<<<dim3(NDIM / BN, MDIM / BM), NTHREADS, SMEM_MAIN>>>(out);
    // 4) out = dots / max(s_i * e_j, eps)
    finalize_kernel<<<MDIM, 256>>>(out);
}